// round 9
// baseline (speedup 1.0000x reference)
#include <cuda_runtime.h>
#include <cuda_bf16.h>
#include <cstdint>

#define D 128
#define NMAX 50000
#define NPAD 50176          // 1024 * 49
#define EMAX 600000
#define SCAN_CHUNK 49       // NPAD / 1024

// ---------------------------------------------------------------------------
// Scratch (__device__ globals per allocation rules)
// ---------------------------------------------------------------------------
__device__ __align__(16) float         g_agg[NPAD * D];   // neighbor sums (fully overwritten)
__device__ __align__(16) __nv_bfloat16 g_w1tH[D * D];     // W1^T hi [col][k]
__device__ __align__(16) __nv_bfloat16 g_w1tL[D * D];     // W1^T lo
__device__ __align__(16) __nv_bfloat16 g_w2tH[D * D];     // W2^T hi
__device__ __align__(16) __nv_bfloat16 g_w2tL[D * D];     // W2^T lo
__device__ __align__(16) float         g_stats[2 * D];    // col sum/sumsq -> scale/shift
__device__ int g_cnt[NPAD];        // per-dst edge counts
__device__ int g_off[NPAD + 1];    // CSR offsets
__device__ int g_cur[NPAD];        // scatter cursors
__device__ int g_srcs[EMAX];       // edge sources grouped by dst

// ---------------------------------------------------------------------------
// PTX helpers (portable ISA only — tcgen05 unavailable on compute_103 target)
// ---------------------------------------------------------------------------
__device__ __forceinline__ void cp16(uint32_t dst, const void* src) {
    asm volatile("cp.async.cg.shared.global [%0], [%1], 16;" :: "r"(dst), "l"(src));
}
__device__ __forceinline__ void cp_commit() { asm volatile("cp.async.commit_group;"); }
template <int N>
__device__ __forceinline__ void cp_wait() {
    asm volatile("cp.async.wait_group %0;" :: "n"(N));
}
__device__ __forceinline__ uint32_t smem_u32(const void* p) {
    return (uint32_t)__cvta_generic_to_shared(p);
}
__device__ __forceinline__ void mma16816(float* c, const uint32_t* a, const uint32_t* b) {
    asm volatile(
        "mma.sync.aligned.m16n8k16.row.col.f32.bf16.bf16.f32 "
        "{%0,%1,%2,%3}, {%4,%5,%6,%7}, {%8,%9}, {%0,%1,%2,%3};"
        : "+f"(c[0]), "+f"(c[1]), "+f"(c[2]), "+f"(c[3])
        : "r"(a[0]), "r"(a[1]), "r"(a[2]), "r"(a[3]), "r"(b[0]), "r"(b[1]));
}
__device__ __forceinline__ void ldsm4(uint32_t* r, uint32_t addr) {
    asm volatile("ldmatrix.sync.aligned.m8n8.x4.shared.b16 {%0,%1,%2,%3}, [%4];"
                 : "=r"(r[0]), "=r"(r[1]), "=r"(r[2]), "=r"(r[3]) : "r"(addr));
}

// Padded row stride 136 halves (272 B): ldmatrix / STS rows hit distinct bank
// quads (68 mod 32 = 4), conflict-free.
#define SH 136
#define TILE_B (128 * SH * 2)            // 34816 B : one weight tile (hi or lo)
#define TILE_A (64 * SH * 2)             // 17408 B : one A/Y tile (hi or lo)
#define OFF_A   (4 * TILE_B)             // A/Y hi
#define OFF_AL  (OFF_A + TILE_A)         // A/Y lo
#define OFF_BIAS (OFF_A + 2 * TILE_A)
#define SMEM_FUSED (OFF_BIAS + 1024)     // 175104 B -> 1 CTA/SM

// ---------------------------------------------------------------------------
// CSR build: zero counts/stats -> histogram -> 1-block scan -> reorder
// ---------------------------------------------------------------------------
__global__ void k_cnt0() {
    int i = blockIdx.x * blockDim.x + threadIdx.x;
    if (i < NPAD) g_cnt[i] = 0;
    if (i < 2 * D) g_stats[i] = 0.0f;
}

__global__ void k_hist(const int* __restrict__ ei, int E) {
    int i = blockIdx.x * blockDim.x + threadIdx.x;
    if (i < E) atomicAdd(&g_cnt[ei[E + i]], 1);
}

__global__ void k_scan() {     // 1 block, 1024 threads, NPAD = 1024*49
    __shared__ int s[1024];
    int t = threadIdx.x;
    int base = t * SCAN_CHUNK;
    int sum = 0;
#pragma unroll 7
    for (int i = 0; i < SCAN_CHUNK; ++i) sum += g_cnt[base + i];
    s[t] = sum;
    __syncthreads();
    for (int off = 1; off < 1024; off <<= 1) {
        int v = (t >= off) ? s[t - off] : 0;
        __syncthreads();
        s[t] += v;
        __syncthreads();
    }
    int run = (t == 0) ? 0 : s[t - 1];
#pragma unroll 7
    for (int i = 0; i < SCAN_CHUNK; ++i) {
        int c = g_cnt[base + i];
        g_off[base + i] = run;
        g_cur[base + i] = run;
        run += c;
    }
    if (t == 1023) g_off[NPAD] = run;
}

__global__ void k_reorder(const int* __restrict__ ei, int E) {
    int i = blockIdx.x * blockDim.x + threadIdx.x;
    if (i >= E) return;
    int src = ei[i];
    int dst = ei[E + i];
    int pos = atomicAdd(&g_cur[dst], 1);
    g_srcs[pos] = src;
}

// ---------------------------------------------------------------------------
// Gather-sum aggregation: one warp per node; lane owns one float4 column.
// Writes each agg row exactly once (plain ST, no atomics).
// ---------------------------------------------------------------------------
__global__ void k_agg(const float* __restrict__ feat, int N) {
    int node = (blockIdx.x * blockDim.x + threadIdx.x) >> 5;
    int lane = threadIdx.x & 31;
    if (node >= N) return;
    int j = g_off[node];
    const int end = g_off[node + 1];
    float4 acc = make_float4(0.f, 0.f, 0.f, 0.f);
    const float4* f4 = reinterpret_cast<const float4*>(feat);
    for (; j + 1 < end; j += 2) {
        int s0 = g_srcs[j], s1 = g_srcs[j + 1];
        float4 v0 = f4[(size_t)s0 * 32 + lane];
        float4 v1 = f4[(size_t)s1 * 32 + lane];
        acc.x += v0.x; acc.y += v0.y; acc.z += v0.z; acc.w += v0.w;
        acc.x += v1.x; acc.y += v1.y; acc.z += v1.z; acc.w += v1.w;
    }
    if (j < end) {
        int s0 = g_srcs[j];
        float4 v0 = f4[(size_t)s0 * 32 + lane];
        acc.x += v0.x; acc.y += v0.y; acc.z += v0.z; acc.w += v0.w;
    }
    reinterpret_cast<float4*>(g_agg)[(size_t)node * 32 + lane] = acc;
}

// ---------------------------------------------------------------------------
// Weight transpose + bf16 split (one-shot, tiny)
// ---------------------------------------------------------------------------
__global__ void k_wt(const float* __restrict__ W1, const float* __restrict__ W2) {
    int i = blockIdx.x * 256 + threadIdx.x;
    if (i < D * D) {
        int k = i >> 7, c = i & 127;
        float w1 = W1[i], w2 = W2[i];
        __nv_bfloat16 h1 = __float2bfloat16(w1);
        __nv_bfloat16 h2 = __float2bfloat16(w2);
        g_w1tH[c * D + k] = h1;
        g_w1tL[c * D + k] = __float2bfloat16(w1 - __bfloat162float(h1));
        g_w2tH[c * D + k] = h2;
        g_w2tL[c * D + k] = __float2bfloat16(w2 - __bfloat162float(h2));
    }
}

// ---------------------------------------------------------------------------
// Persistent fused MLP, 512 threads (16 warps), 64-row tiles.
// Warp grid: warpM = wid&3 (16-row quarters), warpN = wid>>2 (32-col quarters).
// Per tile: A=feat+agg -> bf16 split -> GEMM1 -> y1 in place -> GEMM2 ->
// out + fused BN stats. Weights resident in SMEM for the whole kernel.
// ---------------------------------------------------------------------------
__global__ __launch_bounds__(512, 1)
void k_fused(const float* __restrict__ feat,
             const float* __restrict__ b1, const float* __restrict__ b2,
             float* __restrict__ outF, int M, int nTiles) {
    extern __shared__ __align__(16) uint8_t smem[];
    const uint32_t sBase = smem_u32(smem);
    uint16_t* sAh = reinterpret_cast<uint16_t*>(smem + OFF_A);
    uint16_t* sAl = reinterpret_cast<uint16_t*>(smem + OFF_AL);
    float* s_b1 = reinterpret_cast<float*>(smem + OFF_BIAS);
    float* s_b2 = s_b1 + D;

    const int tid = threadIdx.x;
    const int wid = tid >> 5;
    const int lane = tid & 31;
    const int g = lane >> 2;
    const int l4 = lane & 3;
    const int warpM = wid & 3;       // 4 m-groups of 16 rows
    const int warpN = wid >> 2;      // 4 n-groups of 32 cols

    if (tid < D) s_b1[tid] = b1[tid];
    else if (tid < 2 * D) s_b2[tid - D] = b2[tid - D];

    // ---- Load all 4 weight tiles once (cp.async) ----
#pragma unroll
    for (int t = 0; t < 4; ++t) {
        int idx = tid + t * 512;            // 0..2047 = 128 rows x 16 chunks
        int row = idx >> 4;
        int kb = (idx & 15) * 16;
        uint32_t dOff = (uint32_t)(row * (SH * 2) + kb);
        size_t gOff = (size_t)row * 256 + kb;
        cp16(sBase + dOff,              (const uint8_t*)g_w1tH + gOff);
        cp16(sBase + TILE_B + dOff,     (const uint8_t*)g_w1tL + gOff);
        cp16(sBase + 2 * TILE_B + dOff, (const uint8_t*)g_w2tH + gOff);
        cp16(sBase + 3 * TILE_B + dOff, (const uint8_t*)g_w2tL + gOff);
    }
    cp_commit();
    cp_wait<0>();

    // ---- ldmatrix fragment offsets ----
    const int arow = warpM * 16 + (lane & 7) + ((lane >> 3) & 1) * 8;
    const uint32_t aOff = (uint32_t)((arow * SH + (lane >> 4) * 8) * 2);
    uint32_t bOff[2];
#pragma unroll
    for (int pr = 0; pr < 2; ++pr) {
        int brow = warpN * 32 + pr * 16 + (lane & 7) + (lane >> 4) * 8;
        int bkoff = ((lane >> 3) & 1) * 8;
        bOff[pr] = (uint32_t)((brow * SH + bkoff) * 2);
    }

    // BN stats accumulated across all tiles in registers
    float cs[4][2], cq[4][2];
#pragma unroll
    for (int ni = 0; ni < 4; ++ni) {
        cs[ni][0] = cs[ni][1] = 0.f;
        cq[ni][0] = cq[ni][1] = 0.f;
    }

    float c[4][4];

    auto runGemm = [&](uint32_t aHi, uint32_t aLo, uint32_t bHi, uint32_t bLo) {
#pragma unroll
        for (int ni = 0; ni < 4; ++ni)
#pragma unroll
            for (int e = 0; e < 4; ++e) c[ni][e] = 0.f;
#pragma unroll
        for (int pass = 0; pass < 3; ++pass) {
            const uint32_t aBase = (pass == 2 ? aLo : aHi);
            const uint32_t bBase = (pass == 1 ? bLo : bHi);
#pragma unroll
            for (int ks = 0; ks < 8; ++ks) {
                uint32_t a[4], b[2][4];
                ldsm4(a, aBase + aOff + ks * 32);
                ldsm4(b[0], bBase + bOff[0] + ks * 32);
                ldsm4(b[1], bBase + bOff[1] + ks * 32);
                mma16816(c[0], a, &b[0][0]);
                mma16816(c[1], a, &b[0][2]);
                mma16816(c[2], a, &b[1][0]);
                mma16816(c[3], a, &b[1][2]);
            }
        }
    };

    for (int t = blockIdx.x; t < nTiles; t += gridDim.x) {
        const int rowBase = t * 64;

        __syncthreads();   // previous tile's SMEM reads complete

        // ---- A tile: feat + agg -> bf16 hi/lo split -> SMEM ----
#pragma unroll
        for (int tt = 0; tt < 2; ++tt) {
            int idx = tid + tt * 512;       // 64 rows x 16 chunks of 8 floats
            int row = idx >> 4;
            int kc = (idx & 15) * 8;
            int grow = rowBase + row;
            float h[8];
            if (grow < M) {
                const float4* fp = reinterpret_cast<const float4*>(feat + (size_t)grow * D + kc);
                const float4* ap = reinterpret_cast<const float4*>(g_agg + (size_t)grow * D + kc);
                float4 f0 = fp[0], f1 = fp[1], a0 = ap[0], a1 = ap[1];
                h[0] = f0.x + a0.x; h[1] = f0.y + a0.y; h[2] = f0.z + a0.z; h[3] = f0.w + a0.w;
                h[4] = f1.x + a1.x; h[5] = f1.y + a1.y; h[6] = f1.z + a1.z; h[7] = f1.w + a1.w;
            } else {
#pragma unroll
                for (int e = 0; e < 8; ++e) h[e] = 0.f;
            }
            uint4 hv, lv;
            uint32_t* hp = reinterpret_cast<uint32_t*>(&hv);
            uint32_t* lp = reinterpret_cast<uint32_t*>(&lv);
#pragma unroll
            for (int e = 0; e < 4; ++e) {
                __nv_bfloat162 hh = __floats2bfloat162_rn(h[2 * e], h[2 * e + 1]);
                __nv_bfloat162 ll = __floats2bfloat162_rn(
                    h[2 * e] - __bfloat162float(hh.x),
                    h[2 * e + 1] - __bfloat162float(hh.y));
                hp[e] = *reinterpret_cast<uint32_t*>(&hh);
                lp[e] = *reinterpret_cast<uint32_t*>(&ll);
            }
            *reinterpret_cast<uint4*>(&sAh[row * SH + kc]) = hv;
            *reinterpret_cast<uint4*>(&sAl[row * SH + kc]) = lv;
        }
        __syncthreads();

        // ---- GEMM1: A x W1 ----
        runGemm(sBase + OFF_A, sBase + OFF_AL, sBase, sBase + TILE_B);
        __syncthreads();   // all reads of sA done before overwrite with y1

        // ---- Epilogue 1: y1 = relu(c + b1), split, in place ----
#pragma unroll
        for (int half = 0; half < 2; ++half) {
            const int lrow = warpM * 16 + g + half * 8;
#pragma unroll
            for (int ni = 0; ni < 4; ++ni) {
                const int col = warpN * 32 + ni * 8 + 2 * l4;
                float v0 = fmaxf(c[ni][half * 2 + 0] + s_b1[col], 0.f);
                float v1 = fmaxf(c[ni][half * 2 + 1] + s_b1[col + 1], 0.f);
                __nv_bfloat16 h0 = __float2bfloat16(v0);
                __nv_bfloat16 h1 = __float2bfloat16(v1);
                __nv_bfloat162 hh; hh.x = h0; hh.y = h1;
                __nv_bfloat162 ll = __floats2bfloat162_rn(
                    v0 - __bfloat162float(h0), v1 - __bfloat162float(h1));
                *reinterpret_cast<uint32_t*>(&sAh[lrow * SH + col]) =
                    *reinterpret_cast<uint32_t*>(&hh);
                *reinterpret_cast<uint32_t*>(&sAl[lrow * SH + col]) =
                    *reinterpret_cast<uint32_t*>(&ll);
            }
        }
        __syncthreads();

        // ---- GEMM2: y1 x W2 ----
        runGemm(sBase + OFF_A, sBase + OFF_AL,
                sBase + 2 * TILE_B, sBase + 3 * TILE_B);

        // ---- Epilogue 2: out = relu(c + b2) -> global + BN stats ----
#pragma unroll
        for (int half = 0; half < 2; ++half) {
            const int row = rowBase + warpM * 16 + g + half * 8;
            if (row < M) {
#pragma unroll
                for (int ni = 0; ni < 4; ++ni) {
                    const int col = warpN * 32 + ni * 8 + 2 * l4;
                    float v0 = fmaxf(c[ni][half * 2 + 0] + s_b2[col], 0.f);
                    float v1 = fmaxf(c[ni][half * 2 + 1] + s_b2[col + 1], 0.f);
                    float2 st; st.x = v0; st.y = v1;
                    *reinterpret_cast<float2*>(outF + (size_t)row * D + col) = st;
                    cs[ni][0] += v0; cs[ni][1] += v1;
                    cq[ni][0] += v0 * v0; cq[ni][1] += v1 * v1;
                }
            }
        }
    }

    // ---- Final BN stats reduction (once per CTA) ----
#pragma unroll
    for (int off = 4; off < 32; off <<= 1) {
#pragma unroll
        for (int ni = 0; ni < 4; ++ni) {
#pragma unroll
            for (int e = 0; e < 2; ++e) {
                cs[ni][e] += __shfl_xor_sync(0xFFFFFFFFu, cs[ni][e], off);
                cq[ni][e] += __shfl_xor_sync(0xFFFFFFFFu, cq[ni][e], off);
            }
        }
    }
    __syncthreads();                      // sA region dead -> reduction buffer
    float* redS = reinterpret_cast<float*>(smem + OFF_A);    // [16][32]
    float* redQ = redS + 512;
    if (g == 0) {
#pragma unroll
        for (int ni = 0; ni < 4; ++ni) {
#pragma unroll
            for (int e = 0; e < 2; ++e) {
                int cc = ni * 8 + 2 * l4 + e;
                redS[wid * 32 + cc] = cs[ni][e];
                redQ[wid * 32 + cc] = cq[ni][e];
            }
        }
    }
    __syncthreads();
    if (tid < 128) {
        int wN = tid >> 5;
        int cc = tid & 31;
        float s = 0.f, q = 0.f;
#pragma unroll
        for (int w = 0; w < 4; ++w) {     // wid = wN*4 + warpM
            s += redS[(wN * 4 + w) * 32 + cc];
            q += redQ[(wN * 4 + w) * 32 + cc];
        }
        atomicAdd(&g_stats[tid], s);
        atomicAdd(&g_stats[D + tid], q);
    }
}

// ---------------------------------------------------------------------------
// (sum, sumsq) -> (scale, shift)
// ---------------------------------------------------------------------------
__global__ void k_finalize(const float* __restrict__ gamma,
                           const float* __restrict__ beta, float invN) {
    int c = threadIdx.x;
    float mean = g_stats[c] * invN;
    float var = g_stats[D + c] * invN - mean * mean;
    float scale = gamma[c] * rsqrtf(var + 1e-5f);
    g_stats[c] = scale;
    g_stats[D + c] = beta[c] - mean * scale;
}

// ---------------------------------------------------------------------------
// out = out * scale[col] + shift[col], in place
// ---------------------------------------------------------------------------
__global__ void k_norm(float4* __restrict__ out, int n4) {
    int i = blockIdx.x * blockDim.x + threadIdx.x;
    if (i >= n4) return;
    int c4 = (i & 31) * 4;
    float4 sc = *reinterpret_cast<const float4*>(&g_stats[c4]);
    float4 sh = *reinterpret_cast<const float4*>(&g_stats[D + c4]);
    float4 v = out[i];
    v.x = v.x * sc.x + sh.x;
    v.y = v.y * sc.y + sh.y;
    v.z = v.z * sc.z + sh.z;
    v.w = v.w * sc.w + sh.w;
    out[i] = v;
}

// ---------------------------------------------------------------------------
extern "C" void kernel_launch(void* const* d_in, const int* in_sizes, int n_in,
                              void* d_out, int out_size) {
    const float* feat  = (const float*)d_in[0];
    const int*   ei    = (const int*)d_in[1];
    const float* W1    = (const float*)d_in[2];
    const float* b1    = (const float*)d_in[3];
    const float* W2    = (const float*)d_in[4];
    const float* b2    = (const float*)d_in[5];
    const float* gamma = (const float*)d_in[6];
    const float* beta  = (const float*)d_in[7];
    float* out = (float*)d_out;

    const int N = in_sizes[0] / D;     // 50000
    const int E = in_sizes[1] / 2;     // 600000
    const int n4 = N * D / 4;

    int sms = 148;
    cudaDeviceGetAttribute(&sms, cudaDevAttrMultiProcessorCount, 0);

    cudaFuncSetAttribute(k_fused, cudaFuncAttributeMaxDynamicSharedMemorySize, SMEM_FUSED);

    // CSR aggregation path
    k_cnt0<<<(NPAD + 255) / 256, 256>>>();
    k_wt<<<(D * D + 255) / 256, 256>>>(W1, W2);
    k_hist<<<(E + 255) / 256, 256>>>(ei, E);
    k_scan<<<1, 1024>>>();
    k_reorder<<<(E + 255) / 256, 256>>>(ei, E);
    k_agg<<<(N * 32 + 255) / 256, 256>>>(feat, N);

    // Fused MLP + BN
    k_fused<<<sms, 512, SMEM_FUSED>>>(feat, b1, b2, out, N, (N + 63) / 64);
    k_finalize<<<1, 128>>>(gamma, beta, 1.0f / (float)N);
    k_norm<<<(n4 + 255) / 256, 256>>>((float4*)out, n4);
}

// round 10
// speedup vs baseline: 1.6573x; 1.6573x over previous
#include <cuda_runtime.h>
#include <cuda_bf16.h>
#include <cstdint>

#define D 128
#define NMAX 50000
#define NPAD 50176          // 49 * 1024
#define EMAX 600000
#define NBLK 49             // scan blocks of 1024

// ---------------------------------------------------------------------------
// Scratch (__device__ globals per allocation rules)
// ---------------------------------------------------------------------------
__device__ __align__(16) float         g_agg[NPAD * D];   // neighbor sums (fully overwritten)
__device__ __align__(16) __nv_bfloat16 g_w1tH[D * D];     // W1^T hi [col][k]
__device__ __align__(16) __nv_bfloat16 g_w1tL[D * D];     // W1^T lo
__device__ __align__(16) __nv_bfloat16 g_w2tH[D * D];     // W2^T hi
__device__ __align__(16) __nv_bfloat16 g_w2tL[D * D];     // W2^T lo
__device__ __align__(16) float         g_stats[2 * D];    // col sum/sumsq -> scale/shift
__device__ int g_cnt[NPAD];        // per-dst edge counts
__device__ int g_off[NPAD + 1];    // CSR offsets
__device__ int g_cur[NPAD];        // scatter cursors
__device__ int g_srcs[EMAX];       // edge sources grouped by dst
__device__ int g_bsum[NBLK];       // per-block count sums
__device__ int g_bbase[NBLK];      // exclusive block bases

// ---------------------------------------------------------------------------
// PTX helpers (portable ISA only — tcgen05 unavailable on compute_103 target)
// ---------------------------------------------------------------------------
__device__ __forceinline__ void cp16(uint32_t dst, const void* src) {
    asm volatile("cp.async.cg.shared.global [%0], [%1], 16;" :: "r"(dst), "l"(src));
}
__device__ __forceinline__ void cp_commit() { asm volatile("cp.async.commit_group;"); }
template <int N>
__device__ __forceinline__ void cp_wait() {
    asm volatile("cp.async.wait_group %0;" :: "n"(N));
}
__device__ __forceinline__ uint32_t smem_u32(const void* p) {
    return (uint32_t)__cvta_generic_to_shared(p);
}
__device__ __forceinline__ void mma16816(float* c, const uint32_t* a, const uint32_t* b) {
    asm volatile(
        "mma.sync.aligned.m16n8k16.row.col.f32.bf16.bf16.f32 "
        "{%0,%1,%2,%3}, {%4,%5,%6,%7}, {%8,%9}, {%0,%1,%2,%3};"
        : "+f"(c[0]), "+f"(c[1]), "+f"(c[2]), "+f"(c[3])
        : "r"(a[0]), "r"(a[1]), "r"(a[2]), "r"(a[3]), "r"(b[0]), "r"(b[1]));
}
__device__ __forceinline__ void ldsm4(uint32_t* r, uint32_t addr) {
    asm volatile("ldmatrix.sync.aligned.m8n8.x4.shared.b16 {%0,%1,%2,%3}, [%4];"
                 : "=r"(r[0]), "=r"(r[1]), "=r"(r[2]), "=r"(r[3]) : "r"(addr));
}

// Padded row stride 136 halves (272 B): conflict-free ldmatrix/STS.
#define SH 136
#define TILE_B (128 * SH * 2)            // 34816 B : one weight tile (hi or lo)
#define TILE_A (64 * SH * 2)             // 17408 B : one A/Y tile (hi or lo)
#define OFF_A   (4 * TILE_B)
#define OFF_AL  (OFF_A + TILE_A)
#define OFF_BIAS (OFF_A + 2 * TILE_A)
#define SMEM_FUSED (OFF_BIAS + 1024)     // 175104 B -> 1 CTA/SM

// ---------------------------------------------------------------------------
// CSR build: zero -> histogram -> 3-phase parallel scan -> reorder
// ---------------------------------------------------------------------------
__global__ void k_cnt0() {
    int i = blockIdx.x * blockDim.x + threadIdx.x;
    if (i < NPAD) g_cnt[i] = 0;
    if (i < 2 * D) g_stats[i] = 0.0f;
}

__global__ void k_hist(const int* __restrict__ ei, int E) {
    int i = blockIdx.x * blockDim.x + threadIdx.x;
    if (i < E) atomicAdd(&g_cnt[ei[E + i]], 1);
}

// Phase 1: per-block (1024 counts) reduction -> g_bsum
__global__ void k_bsum() {
    __shared__ int s[32];
    int t = threadIdx.x;
    int v = g_cnt[blockIdx.x * 1024 + t];
#pragma unroll
    for (int off = 16; off > 0; off >>= 1) v += __shfl_xor_sync(0xFFFFFFFFu, v, off);
    if ((t & 31) == 0) s[t >> 5] = v;
    __syncthreads();
    if (t < 32) {
        int w = s[t];
#pragma unroll
        for (int off = 16; off > 0; off >>= 1) w += __shfl_xor_sync(0xFFFFFFFFu, w, off);
        if (t == 0) g_bsum[blockIdx.x] = w;
    }
}

// Phase 2: exclusive scan of 49 block sums (1 warp pair, trivial)
__global__ void k_bscan() {
    int t = threadIdx.x;                 // 64 threads
    int v = (t < NBLK) ? g_bsum[t] : 0;
#pragma unroll
    for (int off = 1; off < 64; off <<= 1) {
        int u = __shfl_up_sync(0xFFFFFFFFu, v, off);
        if ((t & 31) >= off) v += u;
    }
    __shared__ int w0;                   // total of first warp
    if (t == 31) w0 = v;
    __syncthreads();
    if (t >= 32) v += w0;
    if (t < NBLK) g_bbase[t] = v - g_bsum[t];   // exclusive
}

// Phase 3: per-block SMEM scan + base -> g_off / g_cur
__global__ void k_off() {
    __shared__ int s[1024];
    int t = threadIdx.x;
    int gi = blockIdx.x * 1024 + t;
    int c = g_cnt[gi];
    s[t] = c;
    __syncthreads();
    for (int off = 1; off < 1024; off <<= 1) {
        int v = (t >= off) ? s[t - off] : 0;
        __syncthreads();
        s[t] += v;
        __syncthreads();
    }
    int base = g_bbase[blockIdx.x];
    int excl = base + s[t] - c;
    g_off[gi] = excl;
    g_cur[gi] = excl;
    if (gi == NPAD - 1) g_off[NPAD] = base + s[1023];
}

__global__ void k_reorder(const int* __restrict__ ei, int E) {
    int i = blockIdx.x * blockDim.x + threadIdx.x;
    if (i >= E) return;
    int src = ei[i];
    int dst = ei[E + i];
    int pos = atomicAdd(&g_cur[dst], 1);
    g_srcs[pos] = src;
}

// ---------------------------------------------------------------------------
// Gather-sum aggregation: one warp per node; lane owns one float4 column.
// ---------------------------------------------------------------------------
__global__ void k_agg(const float* __restrict__ feat, int N) {
    int node = (blockIdx.x * blockDim.x + threadIdx.x) >> 5;
    int lane = threadIdx.x & 31;
    if (node >= N) return;
    int j = g_off[node];
    const int end = g_off[node + 1];
    float4 acc = make_float4(0.f, 0.f, 0.f, 0.f);
    const float4* f4 = reinterpret_cast<const float4*>(feat);
    for (; j + 1 < end; j += 2) {
        int s0 = g_srcs[j], s1 = g_srcs[j + 1];
        float4 v0 = f4[(size_t)s0 * 32 + lane];
        float4 v1 = f4[(size_t)s1 * 32 + lane];
        acc.x += v0.x; acc.y += v0.y; acc.z += v0.z; acc.w += v0.w;
        acc.x += v1.x; acc.y += v1.y; acc.z += v1.z; acc.w += v1.w;
    }
    if (j < end) {
        int s0 = g_srcs[j];
        float4 v0 = f4[(size_t)s0 * 32 + lane];
        acc.x += v0.x; acc.y += v0.y; acc.z += v0.z; acc.w += v0.w;
    }
    reinterpret_cast<float4*>(g_agg)[(size_t)node * 32 + lane] = acc;
}

// ---------------------------------------------------------------------------
// Weight transpose + bf16 split (one-shot, tiny)
// ---------------------------------------------------------------------------
__global__ void k_wt(const float* __restrict__ W1, const float* __restrict__ W2) {
    int i = blockIdx.x * 256 + threadIdx.x;
    if (i < D * D) {
        int k = i >> 7, c = i & 127;
        float w1 = W1[i], w2 = W2[i];
        __nv_bfloat16 h1 = __float2bfloat16(w1);
        __nv_bfloat16 h2 = __float2bfloat16(w2);
        g_w1tH[c * D + k] = h1;
        g_w1tL[c * D + k] = __float2bfloat16(w1 - __bfloat162float(h1));
        g_w2tH[c * D + k] = h2;
        g_w2tL[c * D + k] = __float2bfloat16(w2 - __bfloat162float(h2));
    }
}

// ---------------------------------------------------------------------------
// Persistent fused MLP, 512 threads (16 warps), 64-row tiles.
// warpM = wid&3 (16-row quarters), warpN = wid>>2 (32-col quarters).
// ---------------------------------------------------------------------------
__global__ __launch_bounds__(512, 1)
void k_fused(const float* __restrict__ feat,
             const float* __restrict__ b1, const float* __restrict__ b2,
             float* __restrict__ outF, int M, int nTiles) {
    extern __shared__ __align__(16) uint8_t smem[];
    const uint32_t sBase = smem_u32(smem);
    uint16_t* sAh = reinterpret_cast<uint16_t*>(smem + OFF_A);
    uint16_t* sAl = reinterpret_cast<uint16_t*>(smem + OFF_AL);
    float* s_b1 = reinterpret_cast<float*>(smem + OFF_BIAS);
    float* s_b2 = s_b1 + D;

    const int tid = threadIdx.x;
    const int wid = tid >> 5;
    const int lane = tid & 31;
    const int g = lane >> 2;
    const int l4 = lane & 3;
    const int warpM = wid & 3;
    const int warpN = wid >> 2;

    if (tid < D) s_b1[tid] = b1[tid];
    else if (tid < 2 * D) s_b2[tid - D] = b2[tid - D];

    // ---- Load all 4 weight tiles once (cp.async) ----
#pragma unroll
    for (int t = 0; t < 4; ++t) {
        int idx = tid + t * 512;
        int row = idx >> 4;
        int kb = (idx & 15) * 16;
        uint32_t dOff = (uint32_t)(row * (SH * 2) + kb);
        size_t gOff = (size_t)row * 256 + kb;
        cp16(sBase + dOff,              (const uint8_t*)g_w1tH + gOff);
        cp16(sBase + TILE_B + dOff,     (const uint8_t*)g_w1tL + gOff);
        cp16(sBase + 2 * TILE_B + dOff, (const uint8_t*)g_w2tH + gOff);
        cp16(sBase + 3 * TILE_B + dOff, (const uint8_t*)g_w2tL + gOff);
    }
    cp_commit();
    cp_wait<0>();

    // ---- ldmatrix fragment offsets ----
    const int arow = warpM * 16 + (lane & 7) + ((lane >> 3) & 1) * 8;
    const uint32_t aOff = (uint32_t)((arow * SH + (lane >> 4) * 8) * 2);
    uint32_t bOff[2];
#pragma unroll
    for (int pr = 0; pr < 2; ++pr) {
        int brow = warpN * 32 + pr * 16 + (lane & 7) + (lane >> 4) * 8;
        int bkoff = ((lane >> 3) & 1) * 8;
        bOff[pr] = (uint32_t)((brow * SH + bkoff) * 2);
    }

    float cs[4][2], cq[4][2];
#pragma unroll
    for (int ni = 0; ni < 4; ++ni) {
        cs[ni][0] = cs[ni][1] = 0.f;
        cq[ni][0] = cq[ni][1] = 0.f;
    }

    float c[4][4];

    auto runGemm = [&](uint32_t aHi, uint32_t aLo, uint32_t bHi, uint32_t bLo) {
#pragma unroll
        for (int ni = 0; ni < 4; ++ni)
#pragma unroll
            for (int e = 0; e < 4; ++e) c[ni][e] = 0.f;
#pragma unroll
        for (int pass = 0; pass < 3; ++pass) {
            const uint32_t aBase = (pass == 2 ? aLo : aHi);
            const uint32_t bBase = (pass == 1 ? bLo : bHi);
#pragma unroll
            for (int ks = 0; ks < 8; ++ks) {
                uint32_t a[4], b[2][4];
                ldsm4(a, aBase + aOff + ks * 32);
                ldsm4(b[0], bBase + bOff[0] + ks * 32);
                ldsm4(b[1], bBase + bOff[1] + ks * 32);
                mma16816(c[0], a, &b[0][0]);
                mma16816(c[1], a, &b[0][2]);
                mma16816(c[2], a, &b[1][0]);
                mma16816(c[3], a, &b[1][2]);
            }
        }
    };

    for (int t = blockIdx.x; t < nTiles; t += gridDim.x) {
        const int rowBase = t * 64;

        __syncthreads();

        // ---- A tile: feat + agg -> bf16 hi/lo split -> SMEM ----
#pragma unroll
        for (int tt = 0; tt < 2; ++tt) {
            int idx = tid + tt * 512;
            int row = idx >> 4;
            int kc = (idx & 15) * 8;
            int grow = rowBase + row;
            float h[8];
            if (grow < M) {
                const float4* fp = reinterpret_cast<const float4*>(feat + (size_t)grow * D + kc);
                const float4* ap = reinterpret_cast<const float4*>(g_agg + (size_t)grow * D + kc);
                float4 f0 = fp[0], f1 = fp[1], a0 = ap[0], a1 = ap[1];
                h[0] = f0.x + a0.x; h[1] = f0.y + a0.y; h[2] = f0.z + a0.z; h[3] = f0.w + a0.w;
                h[4] = f1.x + a1.x; h[5] = f1.y + a1.y; h[6] = f1.z + a1.z; h[7] = f1.w + a1.w;
            } else {
#pragma unroll
                for (int e = 0; e < 8; ++e) h[e] = 0.f;
            }
            uint4 hv, lv;
            uint32_t* hp = reinterpret_cast<uint32_t*>(&hv);
            uint32_t* lp = reinterpret_cast<uint32_t*>(&lv);
#pragma unroll
            for (int e = 0; e < 4; ++e) {
                __nv_bfloat162 hh = __floats2bfloat162_rn(h[2 * e], h[2 * e + 1]);
                __nv_bfloat162 ll = __floats2bfloat162_rn(
                    h[2 * e] - __bfloat162float(hh.x),
                    h[2 * e + 1] - __bfloat162float(hh.y));
                hp[e] = *reinterpret_cast<uint32_t*>(&hh);
                lp[e] = *reinterpret_cast<uint32_t*>(&ll);
            }
            *reinterpret_cast<uint4*>(&sAh[row * SH + kc]) = hv;
            *reinterpret_cast<uint4*>(&sAl[row * SH + kc]) = lv;
        }
        __syncthreads();

        // ---- GEMM1 ----
        runGemm(sBase + OFF_A, sBase + OFF_AL, sBase, sBase + TILE_B);
        __syncthreads();

        // ---- Epilogue 1: y1 = relu(c+b1), split, in place ----
#pragma unroll
        for (int half = 0; half < 2; ++half) {
            const int lrow = warpM * 16 + g + half * 8;
#pragma unroll
            for (int ni = 0; ni < 4; ++ni) {
                const int col = warpN * 32 + ni * 8 + 2 * l4;
                float v0 = fmaxf(c[ni][half * 2 + 0] + s_b1[col], 0.f);
                float v1 = fmaxf(c[ni][half * 2 + 1] + s_b1[col + 1], 0.f);
                __nv_bfloat16 h0 = __float2bfloat16(v0);
                __nv_bfloat16 h1 = __float2bfloat16(v1);
                __nv_bfloat162 hh; hh.x = h0; hh.y = h1;
                __nv_bfloat162 ll = __floats2bfloat162_rn(
                    v0 - __bfloat162float(h0), v1 - __bfloat162float(h1));
                *reinterpret_cast<uint32_t*>(&sAh[lrow * SH + col]) =
                    *reinterpret_cast<uint32_t*>(&hh);
                *reinterpret_cast<uint32_t*>(&sAl[lrow * SH + col]) =
                    *reinterpret_cast<uint32_t*>(&ll);
            }
        }
        __syncthreads();

        // ---- GEMM2 ----
        runGemm(sBase + OFF_A, sBase + OFF_AL,
                sBase + 2 * TILE_B, sBase + 3 * TILE_B);

        // ---- Epilogue 2: out = relu(c+b2) -> global + BN stats ----
#pragma unroll
        for (int half = 0; half < 2; ++half) {
            const int row = rowBase + warpM * 16 + g + half * 8;
            if (row < M) {
#pragma unroll
                for (int ni = 0; ni < 4; ++ni) {
                    const int col = warpN * 32 + ni * 8 + 2 * l4;
                    float v0 = fmaxf(c[ni][half * 2 + 0] + s_b2[col], 0.f);
                    float v1 = fmaxf(c[ni][half * 2 + 1] + s_b2[col + 1], 0.f);
                    float2 st; st.x = v0; st.y = v1;
                    *reinterpret_cast<float2*>(outF + (size_t)row * D + col) = st;
                    cs[ni][0] += v0; cs[ni][1] += v1;
                    cq[ni][0] += v0 * v0; cq[ni][1] += v1 * v1;
                }
            }
        }
    }

    // ---- Final BN stats reduction ----
#pragma unroll
    for (int off = 4; off < 32; off <<= 1) {
#pragma unroll
        for (int ni = 0; ni < 4; ++ni) {
#pragma unroll
            for (int e = 0; e < 2; ++e) {
                cs[ni][e] += __shfl_xor_sync(0xFFFFFFFFu, cs[ni][e], off);
                cq[ni][e] += __shfl_xor_sync(0xFFFFFFFFu, cq[ni][e], off);
            }
        }
    }
    __syncthreads();
    float* redS = reinterpret_cast<float*>(smem + OFF_A);    // [16][32]
    float* redQ = redS + 512;
    if (g == 0) {
#pragma unroll
        for (int ni = 0; ni < 4; ++ni) {
#pragma unroll
            for (int e = 0; e < 2; ++e) {
                int cc = ni * 8 + 2 * l4 + e;
                redS[wid * 32 + cc] = cs[ni][e];
                redQ[wid * 32 + cc] = cq[ni][e];
            }
        }
    }
    __syncthreads();
    if (tid < 128) {
        int wN = tid >> 5;
        int cc = tid & 31;
        float s = 0.f, q = 0.f;
#pragma unroll
        for (int w = 0; w < 4; ++w) {
            s += redS[(wN * 4 + w) * 32 + cc];
            q += redQ[(wN * 4 + w) * 32 + cc];
        }
        atomicAdd(&g_stats[tid], s);
        atomicAdd(&g_stats[D + tid], q);
    }
}

// ---------------------------------------------------------------------------
__global__ void k_finalize(const float* __restrict__ gamma,
                           const float* __restrict__ beta, float invN) {
    int c = threadIdx.x;
    float mean = g_stats[c] * invN;
    float var = g_stats[D + c] * invN - mean * mean;
    float scale = gamma[c] * rsqrtf(var + 1e-5f);
    g_stats[c] = scale;
    g_stats[D + c] = beta[c] - mean * scale;
}

__global__ void k_norm(float4* __restrict__ out, int n4) {
    int i = blockIdx.x * blockDim.x + threadIdx.x;
    if (i >= n4) return;
    int c4 = (i & 31) * 4;
    float4 sc = *reinterpret_cast<const float4*>(&g_stats[c4]);
    float4 sh = *reinterpret_cast<const float4*>(&g_stats[D + c4]);
    float4 v = out[i];
    v.x = v.x * sc.x + sh.x;
    v.y = v.y * sc.y + sh.y;
    v.z = v.z * sc.z + sh.z;
    v.w = v.w * sc.w + sh.w;
    out[i] = v;
}

// ---------------------------------------------------------------------------
extern "C" void kernel_launch(void* const* d_in, const int* in_sizes, int n_in,
                              void* d_out, int out_size) {
    const float* feat  = (const float*)d_in[0];
    const int*   ei    = (const int*)d_in[1];
    const float* W1    = (const float*)d_in[2];
    const float* b1    = (const float*)d_in[3];
    const float* W2    = (const float*)d_in[4];
    const float* b2    = (const float*)d_in[5];
    const float* gamma = (const float*)d_in[6];
    const float* beta  = (const float*)d_in[7];
    float* out = (float*)d_out;

    const int N = in_sizes[0] / D;     // 50000
    const int E = in_sizes[1] / 2;     // 600000
    const int n4 = N * D / 4;

    int sms = 148;
    cudaDeviceGetAttribute(&sms, cudaDevAttrMultiProcessorCount, 0);

    cudaFuncSetAttribute(k_fused, cudaFuncAttributeMaxDynamicSharedMemorySize, SMEM_FUSED);

    // CSR aggregation path (parallel scan)
    k_cnt0<<<(NPAD + 255) / 256, 256>>>();
    k_wt<<<(D * D + 255) / 256, 256>>>(W1, W2);
    k_hist<<<(E + 255) / 256, 256>>>(ei, E);
    k_bsum<<<NBLK, 1024>>>();
    k_bscan<<<1, 64>>>();
    k_off<<<NBLK, 1024>>>();
    k_reorder<<<(E + 255) / 256, 256>>>(ei, E);
    k_agg<<<(N * 32 + 255) / 256, 256>>>(feat, N);

    // Fused MLP + BN
    k_fused<<<sms, 512, SMEM_FUSED>>>(feat, b1, b2, out, N, (N + 63) / 64);
    k_finalize<<<1, 128>>>(gamma, beta, 1.0f / (float)N);
    k_norm<<<(n4 + 255) / 256, 256>>>((float4*)out, n4);
}